// round 16
// baseline (speedup 1.0000x reference)
#include <cuda_runtime.h>
#include <cstdint>
#include <cstddef>

#define BATCH 128
#define SEQT  1024
#define VD    256
#define TPB   256
#define BV    (BATCH * VD)

// ---------------- device scratch (static, no allocation) ----------------
__device__ float g_xp[134217728];                        // x_proj1 permuted [T][cg8][g4][b128][col32]
__device__ float g_h2s[BATCH * SEQT * VD];               // layer-2 hidden states [B,T,V] (fc input)
__device__ __align__(128) float g_hbuf1[2 * BV];         // h1 exchange ring (2 slots)
__device__ __align__(128) float g_hbuf2[2 * BV];         // h2 exchange ring (2 slots)
__device__ float g_wn[VD * VD];                          // row-normalized fc weight
// per-group flag barrier: 8 groups x 16 CTA flags (one 128B line each)
__device__ __align__(128) unsigned g_flag[8 * 32];

// ---------------- packed f32x2 helpers ----------------
__device__ __forceinline__ float2 fma2(float2 acc, float2 w, float2 v) {
    unsigned long long ua, uw, uv;
    ua = *reinterpret_cast<unsigned long long*>(&acc);
    uw = *reinterpret_cast<unsigned long long*>(&w);
    uv = *reinterpret_cast<unsigned long long*>(&v);
    asm("fma.rn.f32x2 %0, %1, %2, %0;" : "+l"(ua) : "l"(uw), "l"(uv));
    return *reinterpret_cast<float2*>(&ua);
}

__device__ __forceinline__ float sigmoidf_(float x) {
    return 1.0f / (1.0f + __expf(-x));
}

// scalar 8-lane butterfly over lane bits 0..2 (kq); result valid on kq==0
__device__ __forceinline__ float red8(float2 a) {
    float s = a.x + a.y;
    s += __shfl_xor_sync(0xffffffffu, s, 1);
    s += __shfl_xor_sync(0xffffffffu, s, 2);
    s += __shfl_xor_sync(0xffffffffu, s, 4);
    return s;
}

__device__ __forceinline__ unsigned ld_acq(const unsigned* p) {
    unsigned v;
    asm volatile("ld.acquire.gpu.global.u32 %0, [%1];" : "=r"(v) : "l"(p) : "memory");
    return v;
}

__device__ __forceinline__ void exch_release(unsigned* p, unsigned v) {
    unsigned d;
    asm volatile("atom.release.gpu.global.exch.b32 %0, [%1], %2;"
                 : "=r"(d) : "l"(p), "r"(v) : "memory");
}

// =======================================================================
// GEMM (layer-1 input projection): x_proj[m][n] = x[m,:].W1[n,:] + b
// BM128/BN128/BK8, TM8/TN8, cumulative B stagger. Permuted output.
// =======================================================================
#define GBK 8

__global__ void __launch_bounds__(256)
gemm_xproj(const float* __restrict__ A, const float* __restrict__ W,
           const float* __restrict__ bih, const float* __restrict__ bhh) {
    __shared__ float As[2][GBK][132];
    __shared__ float Bs[2][GBK][144];

    const int tid = threadIdx.x;
    const int m0 = blockIdx.x * 128;
    const int n0 = blockIdx.y * 128;
    const int tx = tid & 15;
    const int ty = tid >> 4;

    const int lr = tid >> 1;
    const int lc = (tid & 1) * 4;
    const int bsh = 4 * (lr >> 5);
    const int rsh = 4 * (tx >> 2);

    const float* Aptr = A + (size_t)(m0 + lr) * 256 + lc;
    const float* Wptr = W + (size_t)(n0 + lr) * 256 + lc;

    float2 acc[8][4];
#pragma unroll
    for (int i = 0; i < 8; ++i)
#pragma unroll
        for (int j = 0; j < 4; ++j) acc[i][j] = make_float2(0.f, 0.f);

    float4 la = *(const float4*)(Aptr);
    float4 lb = *(const float4*)(Wptr);
#pragma unroll
    for (int i = 0; i < 4; ++i) {
        As[0][lc + i][lr]       = (&la.x)[i];
        Bs[0][lc + i][lr + bsh] = (&lb.x)[i];
    }
    __syncthreads();

    for (int kt = 0; kt < 32; ++kt) {
        const int buf = kt & 1;
        if (kt < 31) {
            la = *(const float4*)(Aptr + (kt + 1) * 8);
            lb = *(const float4*)(Wptr + (kt + 1) * 8);
        }
#pragma unroll
        for (int kk = 0; kk < GBK; ++kk) {
            float4 a0 = *(const float4*)&As[buf][kk][ty * 8];
            float4 a1 = *(const float4*)&As[buf][kk][ty * 8 + 4];
            float4 b0 = *(const float4*)&Bs[buf][kk][tx * 8 + rsh];
            float4 b1 = *(const float4*)&Bs[buf][kk][tx * 8 + 4 + rsh];
            float2 bp[4];
            bp[0] = make_float2(b0.x, b0.y);
            bp[1] = make_float2(b0.z, b0.w);
            bp[2] = make_float2(b1.x, b1.y);
            bp[3] = make_float2(b1.z, b1.w);
            float av[8] = {a0.x, a0.y, a0.z, a0.w, a1.x, a1.y, a1.z, a1.w};
#pragma unroll
            for (int mi = 0; mi < 8; ++mi) {
                float2 ap = make_float2(av[mi], av[mi]);
                acc[mi][0] = fma2(acc[mi][0], ap, bp[0]);
                acc[mi][1] = fma2(acc[mi][1], ap, bp[1]);
                acc[mi][2] = fma2(acc[mi][2], ap, bp[2]);
                acc[mi][3] = fma2(acc[mi][3], ap, bp[3]);
            }
        }
        if (kt < 31) {
            const int nb = buf ^ 1;
#pragma unroll
            for (int i = 0; i < 4; ++i) {
                As[nb][lc + i][lr]       = (&la.x)[i];
                Bs[nb][lc + i][lr + bsh] = (&lb.x)[i];
            }
        }
        __syncthreads();
    }

    const int n = n0 + tx * 8;
    float4 bi0 = *(const float4*)(bih + n);
    float4 bh0 = *(const float4*)(bhh + n);
    float4 bi1 = *(const float4*)(bih + n + 4);
    float4 bh1 = *(const float4*)(bhh + n + 4);
    float4 ba = make_float4(bi0.x + bh0.x, bi0.y + bh0.y, bi0.z + bh0.z, bi0.w + bh0.w);
    float4 bb4 = make_float4(bi1.x + bh1.x, bi1.y + bh1.y, bi1.z + bh1.z, bi1.w + bh1.w);

    const int g      = n >> 8;
    const int col256 = n & 255;
    const int cg     = col256 >> 5;
    const int j0     = col256 & 31;
    const int bb     = m0 >> 10;
    const int t0     = (m0 & 1023) + ty * 8;
#pragma unroll
    for (int mi = 0; mi < 8; ++mi) {
        float4 o0, o1;
        o0.x = acc[mi][0].x + ba.x;
        o0.y = acc[mi][0].y + ba.y;
        o0.z = acc[mi][1].x + ba.z;
        o0.w = acc[mi][1].y + ba.w;
        o1.x = acc[mi][2].x + bb4.x;
        o1.y = acc[mi][2].y + bb4.y;
        o1.z = acc[mi][3].x + bb4.z;
        o1.w = acc[mi][3].y + bb4.w;
        float* dst = g_xp + ((((size_t)(t0 + mi) * 8 + cg) * 4 + g) * 128 + bb) * 32 + j0;
        *(float4*)(dst)     = o0;
        *(float4*)(dst + 4) = o1;
    }
}

// =======================================================================
// Fused two-layer pipelined recurrence (structure identical to the R14
// PASSING version; inner loops de-ILP'd to single-batch to avoid register
// spill: live set ~230 regs < 255).
// =======================================================================
#define H2OFF 1153

__global__ void __launch_bounds__(TPB, 1)
lstm_fused(const float* __restrict__ Whh1,
           const float* __restrict__ Wih2, const float* __restrict__ Whh2,
           const float* __restrict__ bih2, const float* __restrict__ bhh2) {
    const int tid  = threadIdx.x;
    const int lane = tid & 31;
    const int warp = tid >> 5;
    const int cgrp = blockIdx.x & 15;
    const int bgrp = blockIdx.x >> 4;

    const int kq = lane & 7;
    const int rq = lane >> 3;

    // ---- L1 weights: rows warp*8+rq, +4; 32-k slice kq ----
    float2 Wr1[2][16];
#pragma unroll
    for (int i = 0; i < 2; ++i) {
        const int r = warp * 8 + rq + i * 4;           // 0..63
        const int col256 = cgrp * 16 + (r & 15);
        const int row = (r >> 4) * VD + col256;
        const float4* ws = (const float4*)(Whh1 + (size_t)row * VD + kq * 32);
#pragma unroll
        for (int c8 = 0; c8 < 8; ++c8) {
            float4 w4 = ws[c8];
            Wr1[i][2 * c8]     = make_float2(w4.x, w4.y);
            Wr1[i][2 * c8 + 1] = make_float2(w4.z, w4.w);
        }
    }

    // ---- L2 weights: same rows; 64-k slice: kq<4 -> Wih2, kq>=4 -> Whh2 ----
    float2 Wr2[2][32];
#pragma unroll
    for (int i = 0; i < 2; ++i) {
        const int r = warp * 8 + rq + i * 4;
        const int col256 = cgrp * 16 + (r & 15);
        const int row = (r >> 4) * VD + col256;
        const float* base = (kq < 4) ? (Wih2 + (size_t)row * VD + kq * 64)
                                     : (Whh2 + (size_t)row * VD + (kq - 4) * 64);
        const float4* ws = (const float4*)base;
#pragma unroll
        for (int c = 0; c < 16; ++c) {
            float4 w4 = ws[c];
            Wr2[i][2 * c]     = make_float2(w4.x, w4.y);
            Wr2[i][2 * c + 1] = make_float2(w4.z, w4.w);
        }
    }

    // cell ownership: thread -> (batch b_loc = tid>>4, col col_l = tid&15)
    const int b_loc  = tid >> 4;
    const int col_l  = tid & 15;
    const int col256 = cgrp * 16 + col_l;
    const int b_glob = bgrp * 16 + b_loc;
    float c1 = 0.f, c2 = 0.f;

    float bias2[4];
#pragma unroll
    for (int g = 0; g < 4; ++g)
        bias2[g] = bih2[g * VD + col256] + bhh2[g * VD + col256];

    const int xcg = col256 >> 5;
    const int xj0 = col256 & 31;

    __shared__ float4 hx_sm[H2OFF + 16 * 72];   // h1 [0,1152), h2 [1153,2305)
    __shared__ float  gates1[16][80];
    __shared__ float  gates2[16][80];

    unsigned* flags = &g_flag[bgrp * 32];
    const unsigned gen0 = *(volatile unsigned*)&flags[cgrp];

    float xg[4];
#pragma unroll
    for (int g = 0; g < 4; ++g)
        xg[g] = __ldcs(g_xp + ((((size_t)0 * 8 + xcg) * 4 + g) * 128 + b_glob) * 32 + xj0);

    for (int n = 0; n <= SEQT; ++n) {
        // ---- stage h1(n-1) and h2(n-2): 4 f4/thread each ----
        {
            const float4 z = make_float4(0.f, 0.f, 0.f, 0.f);
            const float4* s1 = (const float4*)(g_hbuf1 + (size_t)((n - 1) & 1) * BV) + bgrp * 1024;
            const float4* s2 = (const float4*)(g_hbuf2 + (size_t)(n & 1) * BV) + bgrp * 1024;
#pragma unroll
            for (int i = 0; i < 4; ++i) {
                const int flat = tid + i * 256;          // 0..1023
                const int b  = flat >> 6;
                const int c4 = flat & 63;
                const int dst = b * 72 + (c4 >> 3) * 9 + (c4 & 7);
                hx_sm[dst]         = (n == 0) ? z : __ldcg(s1 + flat);
                hx_sm[H2OFF + dst] = (n <= 1) ? z : __ldcg(s2 + flat);
            }
        }
        __syncthreads();

        // ---- L1 gates: h1(n-1) . Whh1^T (single batch per iter) ----
        if (n < SEQT) {
#pragma unroll 1
            for (int bp = 0; bp < 16; ++bp) {
                const float4* hA = hx_sm + bp * 72 + kq * 9;
                float2 a0 = make_float2(0.f, 0.f), a1 = make_float2(0.f, 0.f);
#pragma unroll
                for (int c8 = 0; c8 < 8; ++c8) {
                    float4 hvA = hA[c8];
                    float2 hA01 = make_float2(hvA.x, hvA.y);
                    float2 hA23 = make_float2(hvA.z, hvA.w);
                    a0 = fma2(a0, Wr1[0][2 * c8],     hA01);
                    a0 = fma2(a0, Wr1[0][2 * c8 + 1], hA23);
                    a1 = fma2(a1, Wr1[1][2 * c8],     hA01);
                    a1 = fma2(a1, Wr1[1][2 * c8 + 1], hA23);
                }
                const float s0 = red8(a0);
                const float s1 = red8(a1);
                if (kq == 0) {
                    const int rb = warp * 8 + rq;
                    gates1[bp][rb]     = s0;
                    gates1[bp][rb + 4] = s1;
                }
            }
        }

        // ---- L2 gates: [h1(n-1), h2(n-2)] . [Wih2;Whh2]^T (single batch) ----
        if (n >= 1) {
            const int hbase = (kq < 4) ? 0 : H2OFF;
            const int s0q = (kq & 3) * 2;
#pragma unroll 1
            for (int bp = 0; bp < 16; ++bp) {
                const float4* hA = hx_sm + hbase + bp * 72 + s0q * 9;
                float2 a0 = make_float2(0.f, 0.f), a1 = make_float2(0.f, 0.f);
#pragma unroll
                for (int j = 0; j < 16; ++j) {
                    const int idx = j + (j >= 8 ? 1 : 0);   // two 8-f4 runs, 9-f4 apart
                    float4 hvA = hA[idx];
                    float2 hA01 = make_float2(hvA.x, hvA.y);
                    float2 hA23 = make_float2(hvA.z, hvA.w);
                    a0 = fma2(a0, Wr2[0][2 * j],     hA01);
                    a0 = fma2(a0, Wr2[0][2 * j + 1], hA23);
                    a1 = fma2(a1, Wr2[1][2 * j],     hA01);
                    a1 = fma2(a1, Wr2[1][2 * j + 1], hA23);
                }
                const float s0 = red8(a0);
                const float s1 = red8(a1);
                if (kq == 0) {
                    const int rb = warp * 8 + rq;
                    gates2[bp][rb]     = s0;
                    gates2[bp][rb + 4] = s1;
                }
            }
        }
        __syncthreads();

        // ---- cells ----
        if (n < SEQT) {
            const float gi = gates1[b_loc][col_l]      + xg[0];
            const float gf = gates1[b_loc][16 + col_l] + xg[1];
            const float gc = gates1[b_loc][32 + col_l] + xg[2];
            const float go = gates1[b_loc][48 + col_l] + xg[3];
            const float i_ = sigmoidf_(gi);
            const float f_ = sigmoidf_(gf);
            const float z_ = tanhf(gc);
            const float o_ = sigmoidf_(go);
            c1 = f_ * c1 + i_ * z_;
            const float hv = o_ * tanhf(c1);
            g_hbuf1[(size_t)(n & 1) * BV + b_glob * VD + col256] = hv;
            if (n + 1 < SEQT) {
#pragma unroll
                for (int g = 0; g < 4; ++g)
                    xg[g] = __ldcs(g_xp + ((((size_t)(n + 1) * 8 + xcg) * 4 + g) * 128 + b_glob) * 32 + xj0);
            }
        }
        if (n >= 1) {
            const float gi = gates2[b_loc][col_l]      + bias2[0];
            const float gf = gates2[b_loc][16 + col_l] + bias2[1];
            const float gc = gates2[b_loc][32 + col_l] + bias2[2];
            const float go = gates2[b_loc][48 + col_l] + bias2[3];
            const float i_ = sigmoidf_(gi);
            const float f_ = sigmoidf_(gf);
            const float z_ = tanhf(gc);
            const float o_ = sigmoidf_(go);
            c2 = f_ * c2 + i_ * z_;
            const float hv = o_ * tanhf(c2);
            g_hbuf2[(size_t)((n - 1) & 1) * BV + b_glob * VD + col256] = hv;
            __stcs(g_h2s + ((size_t)b_glob * SEQT + (n - 1)) * VD + col256, hv);
        }

        // ---- per-group flag barrier (16 CTAs) ----
        const unsigned target = gen0 + (unsigned)(n + 1);
        __syncthreads();
        if (tid == 0) exch_release(&flags[cgrp], target);
        if (lane < 16) {
            const unsigned* f = &flags[lane];
            while ((int)(ld_acq(f) - target) < 0) { }
        }
        __syncwarp();
    }
}

// ---------------- fc weight row-normalization (1 warp per row) ----------------
__global__ void __launch_bounds__(32)
norm_fc(const float* __restrict__ w) {
    const int o = blockIdx.x;
    const int lane = threadIdx.x;
    float4 v0 = *(const float4*)(w + o * VD + lane * 8);
    float4 v1 = *(const float4*)(w + o * VD + lane * 8 + 4);
    float s = v0.x * v0.x + v0.y * v0.y + v0.z * v0.z + v0.w * v0.w
            + v1.x * v1.x + v1.y * v1.y + v1.z * v1.z + v1.w * v1.w;
#pragma unroll
    for (int m = 16; m > 0; m >>= 1) s += __shfl_xor_sync(0xffffffffu, s, m);
    const float inv = rsqrtf(s);
    float4 o0 = make_float4(v0.x * inv, v0.y * inv, v0.z * inv, v0.w * inv);
    float4 o1 = make_float4(v1.x * inv, v1.y * inv, v1.z * inv, v1.w * inv);
    *(float4*)(g_wn + o * VD + lane * 8)     = o0;
    *(float4*)(g_wn + o * VD + lane * 8 + 4) = o1;
}

// ---------------- final FC (retiled like gemm_xproj): out = h2s @ wn^T + b ----------------
__global__ void __launch_bounds__(256)
fc_kernel(const float* __restrict__ fc_b, float* __restrict__ out) {
    __shared__ float As[2][GBK][132];
    __shared__ float Bs[2][GBK][144];

    const int tid = threadIdx.x;
    const int m0 = blockIdx.x * 128;   // gridDim.x = 1024
    const int n0 = blockIdx.y * 128;   // gridDim.y = 2
    const int tx = tid & 15;
    const int ty = tid >> 4;

    const int lr = tid >> 1;
    const int lc = (tid & 1) * 4;
    const int bsh = 4 * (lr >> 5);
    const int rsh = 4 * (tx >> 2);

    const float* Aptr = g_h2s + (size_t)(m0 + lr) * 256 + lc;
    const float* Wptr = g_wn  + (size_t)(n0 + lr) * 256 + lc;

    float2 acc[8][4];
#pragma unroll
    for (int i = 0; i < 8; ++i)
#pragma unroll
        for (int j = 0; j < 4; ++j) acc[i][j] = make_float2(0.f, 0.f);

    float4 la = *(const float4*)(Aptr);
    float4 lb = *(const float4*)(Wptr);
#pragma unroll
    for (int i = 0; i < 4; ++i) {
        As[0][lc + i][lr]       = (&la.x)[i];
        Bs[0][lc + i][lr + bsh] = (&lb.x)[i];
    }
    __syncthreads();

    for (int kt = 0; kt < 32; ++kt) {
        const int buf = kt & 1;
        if (kt < 31) {
            la = *(const float4*)(Aptr + (kt + 1) * 8);
            lb = *(const float4*)(Wptr + (kt + 1) * 8);
        }
#pragma unroll
        for (int kk = 0; kk < GBK; ++kk) {
            float4 a0 = *(const float4*)&As[buf][kk][ty * 8];
            float4 a1 = *(const float4*)&As[buf][kk][ty * 8 + 4];
            float4 b0 = *(const float4*)&Bs[buf][kk][tx * 8 + rsh];
            float4 b1 = *(const float4*)&Bs[buf][kk][tx * 8 + 4 + rsh];
            float2 bp[4];
            bp[0] = make_float2(b0.x, b0.y);
            bp[1] = make_float2(b0.z, b0.w);
            bp[2] = make_float2(b1.x, b1.y);
            bp[3] = make_float2(b1.z, b1.w);
            float av[8] = {a0.x, a0.y, a0.z, a0.w, a1.x, a1.y, a1.z, a1.w};
#pragma unroll
            for (int mi = 0; mi < 8; ++mi) {
                float2 ap = make_float2(av[mi], av[mi]);
                acc[mi][0] = fma2(acc[mi][0], ap, bp[0]);
                acc[mi][1] = fma2(acc[mi][1], ap, bp[1]);
                acc[mi][2] = fma2(acc[mi][2], ap, bp[2]);
                acc[mi][3] = fma2(acc[mi][3], ap, bp[3]);
            }
        }
        if (kt < 31) {
            const int nb = buf ^ 1;
#pragma unroll
            for (int i = 0; i < 4; ++i) {
                As[nb][lc + i][lr]       = (&la.x)[i];
                Bs[nb][lc + i][lr + bsh] = (&lb.x)[i];
            }
        }
        __syncthreads();
    }

    const int n = n0 + tx * 8;
    float4 fb0 = *(const float4*)(fc_b + n);
    float4 fb1 = *(const float4*)(fc_b + n + 4);
#pragma unroll
    for (int mi = 0; mi < 8; ++mi) {
        float4 o0, o1;
        o0.x = acc[mi][0].x + fb0.x;
        o0.y = acc[mi][0].y + fb0.y;
        o0.z = acc[mi][1].x + fb0.z;
        o0.w = acc[mi][1].y + fb0.w;
        o1.x = acc[mi][2].x + fb1.x;
        o1.y = acc[mi][2].y + fb1.y;
        o1.z = acc[mi][3].x + fb1.z;
        o1.w = acc[mi][3].y + fb1.w;
        float* dst = out + (size_t)(m0 + ty * 8 + mi) * 256 + n;
        *(float4*)(dst)     = o0;
        *(float4*)(dst + 4) = o1;
    }
}

// ---------------- launch ----------------
extern "C" void kernel_launch(void* const* d_in, const int* in_sizes, int n_in,
                              void* d_out, int out_size) {
    (void)in_sizes; (void)n_in; (void)out_size;
    const float* x    = (const float*)d_in[0];
    const float* Wih1 = (const float*)d_in[1];
    const float* Whh1 = (const float*)d_in[2];
    const float* bih1 = (const float*)d_in[3];
    const float* bhh1 = (const float*)d_in[4];
    const float* Wih2 = (const float*)d_in[5];
    const float* Whh2 = (const float*)d_in[6];
    const float* bih2 = (const float*)d_in[7];
    const float* bhh2 = (const float*)d_in[8];
    const float* fcw  = (const float*)d_in[9];
    const float* fcb  = (const float*)d_in[10];
    float* out = (float*)d_out;

    norm_fc<<<256, 32>>>(fcw);
    dim3 ggrid(1024, 8);
    gemm_xproj<<<ggrid, 256>>>(x, Wih1, bih1, bhh1);
    lstm_fused<<<128, TPB>>>(Whh1, Wih2, Whh2, bih2, bhh2);
    dim3 fgrid(1024, 2);
    fc_kernel<<<fgrid, 256>>>(fcb, out);
}

// round 17
// speedup vs baseline: 1.0856x; 1.0856x over previous
#include <cuda_runtime.h>
#include <cstdint>
#include <cstddef>

#define BATCH 128
#define SEQT  1024
#define VD    256
#define TPB   256

// ---------------- device scratch (static, no allocation) ----------------
__device__ float g_xp[134217728];                       // x_proj permuted [T][cg8][g4][b128][col32]
__device__ float g_h1s[BATCH * SEQT * VD];              // layer-1 hidden states [B,T,V]
__device__ float g_h2s[BATCH * SEQT * VD];              // layer-2 hidden states [B,T,V]
__device__ __align__(128) float g_hbuf[2 * BATCH * VD]; // double-buffered h exchange
__device__ float g_wn[VD * VD];                         // row-normalized fc weight
// per-group flag barrier: 16 groups x 8 CTA flags (first 32B of a 128B line)
__device__ __align__(128) unsigned g_flag[16 * 32];

// ---------------- packed f32x2 helpers ----------------
__device__ __forceinline__ float2 fma2(float2 acc, float2 w, float2 v) {
    unsigned long long ua, uw, uv;
    ua = *reinterpret_cast<unsigned long long*>(&acc);
    uw = *reinterpret_cast<unsigned long long*>(&w);
    uv = *reinterpret_cast<unsigned long long*>(&v);
    asm("fma.rn.f32x2 %0, %1, %2, %0;" : "+l"(ua) : "l"(uw), "l"(uv));
    return *reinterpret_cast<float2*>(&ua);
}

__device__ __forceinline__ float sigmoidf_(float x) {
    return 1.0f / (1.0f + __expf(-x));
}

// scalar 4-lane butterfly over lane bits 0..1 (kq); result valid on kq==0
__device__ __forceinline__ float red4(float2 a) {
    float s = a.x + a.y;
    s += __shfl_xor_sync(0xffffffffu, s, 1);
    s += __shfl_xor_sync(0xffffffffu, s, 2);
    return s;
}

__device__ __forceinline__ unsigned ld_acq(const unsigned* p) {
    unsigned v;
    asm volatile("ld.acquire.gpu.global.u32 %0, [%1];" : "=r"(v) : "l"(p) : "memory");
    return v;
}

__device__ __forceinline__ void exch_release(unsigned* p, unsigned v) {
    unsigned d;
    asm volatile("atom.release.gpu.global.exch.b32 %0, [%1], %2;"
                 : "=r"(d) : "l"(p), "r"(v) : "memory");
}

// =======================================================================
// GEMM: x_proj[m][n] = A[m][0:256] . W[n][0:256] + bih[n] + bhh[n]
// (R12/R13 proven tile: BM128/BN128/BK8, TM8/TN8, cumulative B stagger)
// =======================================================================
#define GBK 8

__global__ void __launch_bounds__(256)
gemm_xproj(const float* __restrict__ A, const float* __restrict__ W,
           const float* __restrict__ bih, const float* __restrict__ bhh) {
    __shared__ float As[2][GBK][132];
    __shared__ float Bs[2][GBK][144];

    const int tid = threadIdx.x;
    const int m0 = blockIdx.x * 128;
    const int n0 = blockIdx.y * 128;
    const int tx = tid & 15;
    const int ty = tid >> 4;

    const int lr = tid >> 1;
    const int lc = (tid & 1) * 4;
    const int bsh = 4 * (lr >> 5);
    const int rsh = 4 * (tx >> 2);

    const float* Aptr = A + (size_t)(m0 + lr) * 256 + lc;
    const float* Wptr = W + (size_t)(n0 + lr) * 256 + lc;

    float2 acc[8][4];
#pragma unroll
    for (int i = 0; i < 8; ++i)
#pragma unroll
        for (int j = 0; j < 4; ++j) acc[i][j] = make_float2(0.f, 0.f);

    float4 la = *(const float4*)(Aptr);
    float4 lb = *(const float4*)(Wptr);
#pragma unroll
    for (int i = 0; i < 4; ++i) {
        As[0][lc + i][lr]       = (&la.x)[i];
        Bs[0][lc + i][lr + bsh] = (&lb.x)[i];
    }
    __syncthreads();

    for (int kt = 0; kt < 32; ++kt) {
        const int buf = kt & 1;
        if (kt < 31) {
            la = *(const float4*)(Aptr + (kt + 1) * 8);
            lb = *(const float4*)(Wptr + (kt + 1) * 8);
        }
#pragma unroll
        for (int kk = 0; kk < GBK; ++kk) {
            float4 a0 = *(const float4*)&As[buf][kk][ty * 8];
            float4 a1 = *(const float4*)&As[buf][kk][ty * 8 + 4];
            float4 b0 = *(const float4*)&Bs[buf][kk][tx * 8 + rsh];
            float4 b1 = *(const float4*)&Bs[buf][kk][tx * 8 + 4 + rsh];
            float2 bp[4];
            bp[0] = make_float2(b0.x, b0.y);
            bp[1] = make_float2(b0.z, b0.w);
            bp[2] = make_float2(b1.x, b1.y);
            bp[3] = make_float2(b1.z, b1.w);
            float av[8] = {a0.x, a0.y, a0.z, a0.w, a1.x, a1.y, a1.z, a1.w};
#pragma unroll
            for (int mi = 0; mi < 8; ++mi) {
                float2 ap = make_float2(av[mi], av[mi]);
                acc[mi][0] = fma2(acc[mi][0], ap, bp[0]);
                acc[mi][1] = fma2(acc[mi][1], ap, bp[1]);
                acc[mi][2] = fma2(acc[mi][2], ap, bp[2]);
                acc[mi][3] = fma2(acc[mi][3], ap, bp[3]);
            }
        }
        if (kt < 31) {
            const int nb = buf ^ 1;
#pragma unroll
            for (int i = 0; i < 4; ++i) {
                As[nb][lc + i][lr]       = (&la.x)[i];
                Bs[nb][lc + i][lr + bsh] = (&lb.x)[i];
            }
        }
        __syncthreads();
    }

    const int n = n0 + tx * 8;
    float4 bi0 = *(const float4*)(bih + n);
    float4 bh0 = *(const float4*)(bhh + n);
    float4 bi1 = *(const float4*)(bih + n + 4);
    float4 bh1 = *(const float4*)(bhh + n + 4);
    float4 ba = make_float4(bi0.x + bh0.x, bi0.y + bh0.y, bi0.z + bh0.z, bi0.w + bh0.w);
    float4 bb4 = make_float4(bi1.x + bh1.x, bi1.y + bh1.y, bi1.z + bh1.z, bi1.w + bh1.w);

    const int g      = n >> 8;
    const int col256 = n & 255;
    const int cg     = col256 >> 5;
    const int j0     = col256 & 31;
    const int bb     = m0 >> 10;
    const int t0     = (m0 & 1023) + ty * 8;
#pragma unroll
    for (int mi = 0; mi < 8; ++mi) {
        float4 o0, o1;
        o0.x = acc[mi][0].x + ba.x;
        o0.y = acc[mi][0].y + ba.y;
        o0.z = acc[mi][1].x + ba.z;
        o0.w = acc[mi][1].y + ba.w;
        o1.x = acc[mi][2].x + bb4.x;
        o1.y = acc[mi][2].y + bb4.y;
        o1.z = acc[mi][3].x + bb4.z;
        o1.w = acc[mi][3].y + bb4.w;
        float* dst = g_xp + ((((size_t)(t0 + mi) * 8 + cg) * 4 + g) * 128 + bb) * 32 + j0;
        *(float4*)(dst)     = o0;
        *(float4*)(dst + 4) = o1;
    }
}

// =======================================================================
// Recurrence, flat grid + per-group flag barrier. 256 threads/CTA.
// Grid: 128 blocks = 16 groups(bgrp) x 8 CTAs(cgrp). Block: 8 batches x
// 32 cols (128 gate rows). Warp w: rows [w*16, w*16+16).
// NEW lane map: kq=lane&3 (64-k slice), rq=lane>>2 (0..7); lane owns rows
// w*16+rq and w*16+8+rq (2 rows x 64 k = 128 weight floats, compile-time
// indexed). Reduction: 2 shfl rounds (32 SHFL/warp/step vs 96 in R13).
// h smem layout [b][kq*17 + c16] (f4, stride 72): 4-address broadcast LDS,
// bank groups {0-3,4-7,8-11,12-15}+4c -> conflict-free.
// =======================================================================
__global__ void __launch_bounds__(TPB, 1)
lstm_rec(const float* __restrict__ Whh, int layer) {
    float* HS = layer ? g_h2s : g_h1s;

    const int tid  = threadIdx.x;
    const int lane = tid & 31;
    const int warp = tid >> 5;
    const int cgrp = blockIdx.x & 7;
    const int bgrp = blockIdx.x >> 3;

    const int kq = lane & 3;     // k-slice: k = kq*64 .. +63
    const int rq = lane >> 2;    // 0..7

    // 2 rows x 32 float2 weights in registers (compile-time indexed)
    float2 Wr[2][32];
#pragma unroll
    for (int i = 0; i < 2; ++i) {
        const int r = warp * 16 + rq + i * 8;
        const int Wrow = (r >> 5) * VD + cgrp * 32 + (r & 31);
        const float4* ws = (const float4*)(Whh + (size_t)Wrow * VD + kq * 64);
#pragma unroll
        for (int c = 0; c < 16; ++c) {
            float4 w4 = ws[c];
            Wr[i][2 * c]     = make_float2(w4.x, w4.y);
            Wr[i][2 * c + 1] = make_float2(w4.z, w4.w);
        }
    }

    // cell ownership: b_loc=tid>>5 (=warp), col=tid&31
    const int b_loc  = tid >> 5;
    const int ccol   = tid & 31;
    const int b_glob = bgrp * 8 + b_loc;
    float cstate = 0.f;

    __shared__ float4 h_sm4[8 * 72];      // [8 b][4 kq-slices @ kq*17][16 f4]
    __shared__ float  gates_sm[8][128];

    const unsigned gen0 = *(volatile unsigned*)&g_flag[bgrp * 32 + cgrp];

    // prefetch x_proj for t=0
    float xg[4];
#pragma unroll
    for (int g = 0; g < 4; ++g)
        xg[g] = __ldcs(g_xp + ((((size_t)0 * 8 + cgrp) * 4 + g) * 128 + b_glob) * 32 + ccol);

    for (int t = 0; t < SEQT; ++t) {
        // ---- stage h(t-1): 512 float4, 2 per thread ----
        if (t == 0) {
            float4 z = make_float4(0.f, 0.f, 0.f, 0.f);
#pragma unroll
            for (int i = 0; i < 2; ++i) {
                const int flat = tid + i * 256;
                const int b  = flat >> 6;
                const int c4 = flat & 63;
                h_sm4[b * 72 + (c4 >> 4) * 17 + (c4 & 15)] = z;
            }
        } else {
            const float4* src = (const float4*)(g_hbuf + (size_t)(t & 1) * (BATCH * VD)) + bgrp * 512;
#pragma unroll
            for (int i = 0; i < 2; ++i) {
                const int flat = tid + i * 256;
                const int b  = flat >> 6;
                const int c4 = flat & 63;
                h_sm4[b * 72 + (c4 >> 4) * 17 + (c4 & 15)] = __ldcg(src + flat);
            }
        }
        __syncthreads();

        // ---- gates = h . Whh^T (2 batches per iteration, 4 acc chains) ----
#pragma unroll
        for (int bp = 0; bp < 8; bp += 2) {
            const float4* hrowA = h_sm4 + bp * 72 + kq * 17;
            const float4* hrowB = hrowA + 72;
            float2 a0 = make_float2(0.f, 0.f), a1 = make_float2(0.f, 0.f);
            float2 b0 = make_float2(0.f, 0.f), b1 = make_float2(0.f, 0.f);
#pragma unroll
            for (int c = 0; c < 16; ++c) {
                float4 hvA = hrowA[c];
                float4 hvB = hrowB[c];
                float2 hA01 = make_float2(hvA.x, hvA.y);
                float2 hA23 = make_float2(hvA.z, hvA.w);
                float2 hB01 = make_float2(hvB.x, hvB.y);
                float2 hB23 = make_float2(hvB.z, hvB.w);
                a0 = fma2(a0, Wr[0][2 * c],     hA01);
                a0 = fma2(a0, Wr[0][2 * c + 1], hA23);
                a1 = fma2(a1, Wr[1][2 * c],     hA01);
                a1 = fma2(a1, Wr[1][2 * c + 1], hA23);
                b0 = fma2(b0, Wr[0][2 * c],     hB01);
                b0 = fma2(b0, Wr[0][2 * c + 1], hB23);
                b1 = fma2(b1, Wr[1][2 * c],     hB01);
                b1 = fma2(b1, Wr[1][2 * c + 1], hB23);
            }
            const float s0 = red4(a0);
            const float s1 = red4(a1);
            const float u0 = red4(b0);
            const float u1 = red4(b1);
            if (kq == 0) {
                const int rb = warp * 16 + rq;
                gates_sm[bp][rb]         = s0;
                gates_sm[bp][rb + 8]     = s1;
                gates_sm[bp + 1][rb]     = u0;
                gates_sm[bp + 1][rb + 8] = u1;
            }
        }
        __syncthreads();

        // ---- cell update: thread owns (batch=b_loc, col=ccol) ----
        {
            const float gi = gates_sm[b_loc][ccol]      + xg[0];
            const float gf = gates_sm[b_loc][32 + ccol] + xg[1];
            const float gc = gates_sm[b_loc][64 + ccol] + xg[2];
            const float go = gates_sm[b_loc][96 + ccol] + xg[3];
            const float i_ = sigmoidf_(gi);
            const float f_ = sigmoidf_(gf);
            const float z_ = tanhf(gc);
            const float o_ = sigmoidf_(go);
            cstate = f_ * cstate + i_ * z_;
            const float hv = o_ * tanhf(cstate);
            g_hbuf[(size_t)((t + 1) & 1) * (BATCH * VD) + b_glob * VD + cgrp * 32 + ccol] = hv;
            __stcs(HS + ((size_t)b_glob * SEQT + t) * VD + cgrp * 32 + ccol, hv);

            // prefetch x_proj for t+1 (hide under barrier)
            if (t + 1 < SEQT) {
#pragma unroll
                for (int g = 0; g < 4; ++g)
                    xg[g] = __ldcs(g_xp + ((((size_t)(t + 1) * 8 + cgrp) * 4 + g) * 128 + b_glob) * 32 + ccol);
            }
        }

        // ---- per-group flag barrier ----
        const unsigned target = gen0 + (unsigned)(t + 1);
        __syncthreads();
        if (tid == 0) exch_release(&g_flag[bgrp * 32 + cgrp], target);
        if (lane < 8) {
            const unsigned* f = &g_flag[bgrp * 32 + lane];
            while ((int)(ld_acq(f) - target) < 0) { }
        }
        __syncwarp();
    }
}

// ---------------- fc weight row-normalization (1 warp per row) ----------------
__global__ void __launch_bounds__(32)
norm_fc(const float* __restrict__ w) {
    const int o = blockIdx.x;
    const int lane = threadIdx.x;
    float4 v0 = *(const float4*)(w + o * VD + lane * 8);
    float4 v1 = *(const float4*)(w + o * VD + lane * 8 + 4);
    float s = v0.x * v0.x + v0.y * v0.y + v0.z * v0.z + v0.w * v0.w
            + v1.x * v1.x + v1.y * v1.y + v1.z * v1.z + v1.w * v1.w;
#pragma unroll
    for (int m = 16; m > 0; m >>= 1) s += __shfl_xor_sync(0xffffffffu, s, m);
    const float inv = rsqrtf(s);
    float4 o0 = make_float4(v0.x * inv, v0.y * inv, v0.z * inv, v0.w * inv);
    float4 o1 = make_float4(v1.x * inv, v1.y * inv, v1.z * inv, v1.w * inv);
    *(float4*)(g_wn + o * VD + lane * 8)     = o0;
    *(float4*)(g_wn + o * VD + lane * 8 + 4) = o1;
}

// ---------------- final FC (retiled like gemm_xproj): out = h2s @ wn^T + b ----------------
__global__ void __launch_bounds__(256)
fc_kernel(const float* __restrict__ fc_b, float* __restrict__ out) {
    __shared__ float As[2][GBK][132];
    __shared__ float Bs[2][GBK][144];

    const int tid = threadIdx.x;
    const int m0 = blockIdx.x * 128;   // gridDim.x = 1024
    const int n0 = blockIdx.y * 128;   // gridDim.y = 2
    const int tx = tid & 15;
    const int ty = tid >> 4;

    const int lr = tid >> 1;
    const int lc = (tid & 1) * 4;
    const int bsh = 4 * (lr >> 5);
    const int rsh = 4 * (tx >> 2);

    const float* Aptr = g_h2s + (size_t)(m0 + lr) * 256 + lc;
    const float* Wptr = g_wn  + (size_t)(n0 + lr) * 256 + lc;

    float2 acc[8][4];
#pragma unroll
    for (int i = 0; i < 8; ++i)
#pragma unroll
        for (int j = 0; j < 4; ++j) acc[i][j] = make_float2(0.f, 0.f);

    float4 la = *(const float4*)(Aptr);
    float4 lb = *(const float4*)(Wptr);
#pragma unroll
    for (int i = 0; i < 4; ++i) {
        As[0][lc + i][lr]       = (&la.x)[i];
        Bs[0][lc + i][lr + bsh] = (&lb.x)[i];
    }
    __syncthreads();

    for (int kt = 0; kt < 32; ++kt) {
        const int buf = kt & 1;
        if (kt < 31) {
            la = *(const float4*)(Aptr + (kt + 1) * 8);
            lb = *(const float4*)(Wptr + (kt + 1) * 8);
        }
#pragma unroll
        for (int kk = 0; kk < GBK; ++kk) {
            float4 a0 = *(const float4*)&As[buf][kk][ty * 8];
            float4 a1 = *(const float4*)&As[buf][kk][ty * 8 + 4];
            float4 b0 = *(const float4*)&Bs[buf][kk][tx * 8 + rsh];
            float4 b1 = *(const float4*)&Bs[buf][kk][tx * 8 + 4 + rsh];
            float2 bp[4];
            bp[0] = make_float2(b0.x, b0.y);
            bp[1] = make_float2(b0.z, b0.w);
            bp[2] = make_float2(b1.x, b1.y);
            bp[3] = make_float2(b1.z, b1.w);
            float av[8] = {a0.x, a0.y, a0.z, a0.w, a1.x, a1.y, a1.z, a1.w};
#pragma unroll
            for (int mi = 0; mi < 8; ++mi) {
                float2 ap = make_float2(av[mi], av[mi]);
                acc[mi][0] = fma2(acc[mi][0], ap, bp[0]);
                acc[mi][1] = fma2(acc[mi][1], ap, bp[1]);
                acc[mi][2] = fma2(acc[mi][2], ap, bp[2]);
                acc[mi][3] = fma2(acc[mi][3], ap, bp[3]);
            }
        }
        if (kt < 31) {
            const int nb = buf ^ 1;
#pragma unroll
            for (int i = 0; i < 4; ++i) {
                As[nb][lc + i][lr]       = (&la.x)[i];
                Bs[nb][lc + i][lr + bsh] = (&lb.x)[i];
            }
        }
        __syncthreads();
    }

    const int n = n0 + tx * 8;
    float4 fb0 = *(const float4*)(fc_b + n);
    float4 fb1 = *(const float4*)(fc_b + n + 4);
#pragma unroll
    for (int mi = 0; mi < 8; ++mi) {
        float4 o0, o1;
        o0.x = acc[mi][0].x + fb0.x;
        o0.y = acc[mi][0].y + fb0.y;
        o0.z = acc[mi][1].x + fb0.z;
        o0.w = acc[mi][1].y + fb0.w;
        o1.x = acc[mi][2].x + fb1.x;
        o1.y = acc[mi][2].y + fb1.y;
        o1.z = acc[mi][3].x + fb1.z;
        o1.w = acc[mi][3].y + fb1.w;
        float* dst = out + (size_t)(m0 + ty * 8 + mi) * 256 + n;
        *(float4*)(dst)     = o0;
        *(float4*)(dst + 4) = o1;
    }
}

// ---------------- launch ----------------
extern "C" void kernel_launch(void* const* d_in, const int* in_sizes, int n_in,
                              void* d_out, int out_size) {
    (void)in_sizes; (void)n_in; (void)out_size;
    const float* x    = (const float*)d_in[0];
    const float* Wih1 = (const float*)d_in[1];
    const float* Whh1 = (const float*)d_in[2];
    const float* bih1 = (const float*)d_in[3];
    const float* bhh1 = (const float*)d_in[4];
    const float* Wih2 = (const float*)d_in[5];
    const float* Whh2 = (const float*)d_in[6];
    const float* bih2 = (const float*)d_in[7];
    const float* bhh2 = (const float*)d_in[8];
    const float* fcw  = (const float*)d_in[9];
    const float* fcb  = (const float*)d_in[10];
    float* out = (float*)d_out;

    float* h1s_ptr = nullptr;
    cudaGetSymbolAddress((void**)&h1s_ptr, g_h1s);

    norm_fc<<<256, 32>>>(fcw);
    dim3 ggrid(1024, 8);
    gemm_xproj<<<ggrid, 256>>>(x, Wih1, bih1, bhh1);
    lstm_rec<<<128, TPB>>>(Whh1, 0);
    gemm_xproj<<<ggrid, 256>>>(h1s_ptr, Wih2, bih2, bhh2);
    lstm_rec<<<128, TPB>>>(Whh2, 1);
    dim3 fgrid(1024, 2);
    fc_kernel<<<fgrid, 256>>>(fcb, out);
}